// round 16
// baseline (speedup 1.0000x reference)
#include <cuda_runtime.h>
#include <cuda_bf16.h>
#include <cstdint>

#define BB 8
#define CC 256
#define HWN 16384
#define KK 64
#define EPS 1e-5f
#define PT1 64       // k1 pixel tile
#define XS1 72       // k1 xs[c][p] row stride
#define PTILE 128    // k3 pixel tile

typedef unsigned long long ull;

// ---------------- helpers ----------------
__device__ __forceinline__ ull pk2(float lo, float hi) {
    ull d; asm("mov.b64 %0, {%1, %2};" : "=l"(d) : "f"(lo), "f"(hi)); return d;
}
__device__ __forceinline__ float2 unpk(ull v) {
    float2 r; asm("mov.b64 {%0, %1}, %2;" : "=f"(r.x), "=f"(r.y) : "l"(v)); return r;
}
__device__ __forceinline__ void ffma2(ull& d, ull a, ull b) {
    asm("fma.rn.f32x2 %0, %1, %2, %0;" : "+l"(d) : "l"(a), "l"(b));
}
__device__ __forceinline__ uint32_t to_tf32(float f) {
    uint32_t u; asm("cvt.rna.tf32.f32 %0, %1;" : "=r"(u) : "f"(f)); return u;
}
__device__ __forceinline__ void tf32split(float v, uint32_t& hi, uint32_t& lo) {
    uint32_t h = to_tf32(v);
    hi = h;
    lo = to_tf32(v - __uint_as_float(h));
}
__device__ __forceinline__ void mma8(float* d, uint32_t a0, uint32_t a1,
                                     uint32_t a2, uint32_t a3,
                                     uint32_t b0, uint32_t b1) {
    asm("mma.sync.aligned.m16n8k8.row.col.f32.tf32.tf32.f32 "
        "{%0,%1,%2,%3}, {%4,%5,%6,%7}, {%8,%9}, {%0,%1,%2,%3};"
        : "+f"(d[0]), "+f"(d[1]), "+f"(d[2]), "+f"(d[3])
        : "r"(a0), "r"(a1), "r"(a2), "r"(a3), "r"(b0), "r"(b1));
}
__device__ __forceinline__ uint32_t fbits(float f) { return __float_as_uint(f); }

// atT swizzled layout, row stride 64 floats = 16 chunks of 16B.
// chunk' = p4 ^ (k&7): conflict-free for lane-varying k over 8 consecutive rows.
__device__ __forceinline__ int atIdx(int k, int p) {
    return k * 64 + ((((p >> 2) ^ (k & 7)) << 2) | (p & 3));
}
__device__ __forceinline__ int atChunk(int k, int p4) {
    return k * 64 + ((p4 ^ (k & 7)) << 2);
}

// ---------------- device scratch (no allocation) ----------------
__device__ float g_attn[(size_t)BB * KK * HWN];   // [b][k][n]  32MB
__device__ float g_cluster[BB * KK * CC];
__device__ float g_A[BB * KK];
__device__ float g_S2[BB * KK * KK];
__device__ float g_AF[32 * 4 * 32 * 4];           // tf32 A-fragments for sim
__device__ float g_ref[BB * KK * CC];             // silu(dwconv) [b][k][c]
__device__ float g_Mhat[BB * KK * CC];            // alpha * Mc  [b][k][o]
__device__ float g_Bc[BB * CC];

// ---------------- init (split launches to keep ncu capture slot on k1) ----------------
__global__ void k_init_a() {
    int i = blockIdx.x * blockDim.x + threadIdx.x;
    int st = gridDim.x * blockDim.x;
    for (int t = i; t < BB * KK * CC; t += st) g_cluster[t] = 0.f;
}
__global__ void k_init_b() {
    int i = blockIdx.x * blockDim.x + threadIdx.x;
    int st = gridDim.x * blockDim.x;
    for (int t = i; t < BB * KK * KK; t += st) g_S2[t] = 0.f;
    for (int t = i; t < BB * KK; t += st) g_A[t] = 0.f;
}
// Pack centers into mma.m16n8k8 A-fragment order, tf32-rounded.
__global__ void k_init_c(const float* __restrict__ centers) {
    int i = blockIdx.x * blockDim.x + threadIdx.x;
    int st = gridDim.x * blockDim.x;
    for (int t = i; t < 32 * 4 * 32 * 4; t += st) {
        int j  = t & 3;
        int l  = (t >> 2) & 31;
        int kt = (t >> 7) & 3;
        int s  = t >> 9;
        int k = kt * 16 + (l >> 2) + 8 * (j & 1);
        int c = s * 8 + (l & 3) + 4 * (j >> 1);
        uint32_t u = to_tf32(centers[k * CC + c]);
        g_AF[t] = __uint_as_float(u);
    }
}

// ---------------- pass 1: mma-sim -> softmax -> attn, A, fused S2+cluster (mma) ----------------
// 256 threads, 64-pixel tile, 2 CTAs/SM. x stored pre-rounded to tf32 (hi-only).
__global__ __launch_bounds__(256, 2) void k1(const float* __restrict__ x) {
    extern __shared__ float s1[];
    float* xsh = s1;                 // [256][72] : tf32-rounded x, xs[c][p]
    float* atT = s1 + CC * XS1;      // swizzled [64]x[64] (logits, then exact attn)

    const int b = blockIdx.y;
    const int pix0 = blockIdx.x * PT1;
    const int tid = threadIdx.x;
    const float* xb = x + (size_t)b * CC * HWN;

    const int w = tid >> 5, l = tid & 31;
    const int lq = l >> 2, lr = l & 3;

    // load x tile: 4096 float4 (16 per thread), tf32-rounded in place
#pragma unroll
    for (int it = 0; it < 16; it++) {
        int idx = it * 256 + tid;
        int c = idx >> 4, p4 = idx & 15;
        float4 v = __ldcs((const float4*)(xb + (size_t)c * HWN + pix0) + p4);
        v.x = __uint_as_float(to_tf32(v.x));
        v.y = __uint_as_float(to_tf32(v.y));
        v.z = __uint_as_float(to_tf32(v.z));
        v.w = __uint_as_float(to_tf32(v.w));
        *((float4*)(xsh + c * XS1) + p4) = v;
    }
    __syncthreads();

    // --- sim via tensor cores: D[64k x 64p] = centers @ x^T (tf32, logits only) ---
    {
        const int kt = w & 3;
        const int k0 = kt * 16;
        const int pbase = (w >> 2) * 32;
        float d[4][4];
#pragma unroll
        for (int t = 0; t < 4; t++)
#pragma unroll
            for (int j = 0; j < 4; j++) d[t][j] = 0.f;

        for (int s = 0; s < 32; s++) {
            float4 af = __ldg(((const float4*)g_AF) + (s * 4 + kt) * 32 + l);
            uint32_t a0 = fbits(af.x), a1 = fbits(af.y);
            uint32_t a2 = fbits(af.z), a3 = fbits(af.w);
            const float* xrow0 = xsh + (8 * s + lr) * XS1 + lq;
            const float* xrow1 = xrow0 + 4 * XS1;
#pragma unroll
            for (int t = 0; t < 4; t++) {
                int p0 = pbase + t * 8;
                mma8(d[t], a0, a1, a2, a3, fbits(xrow0[p0]), fbits(xrow1[p0]));
            }
        }
        const float sc = 0.0625f;   // C^-0.5
#pragma unroll
        for (int t = 0; t < 4; t++) {
            int p0 = pbase + t * 8;
            int kr = k0 + lq, pc = p0 + 2 * lr;
            atT[atIdx(kr,     pc)]     = d[t][0] * sc;
            atT[atIdx(kr,     pc + 1)] = d[t][1] * sc;
            atT[atIdx(kr + 8, pc)]     = d[t][2] * sc;
            atT[atIdx(kr + 8, pc + 1)] = d[t][3] * sc;
        }
    }
    __syncthreads();

    // --- softmax over k per pixel (64 pixels); atT holds exact f32 attn ---
    if (tid < PT1) {
        int p = tid;
        float v[KK];
        float m = -1e30f;
#pragma unroll
        for (int k = 0; k < KK; k++) { v[k] = atT[atIdx(k, p)]; m = fmaxf(m, v[k]); }
        float ssum = 0.f;
#pragma unroll
        for (int k = 0; k < KK; k++) { v[k] = __expf(v[k] - m); ssum += v[k]; }
        float inv = 1.f / ssum;
#pragma unroll
        for (int k = 0; k < KK; k++) atT[atIdx(k, p)] = v[k] * inv;
    }
    __syncthreads();

    // --- attn writeout (1024 float4, 4 per thread) ---
#pragma unroll
    for (int it = 0; it < 4; it++) {
        int idx = it * 256 + tid;
        int k = idx >> 4, p4 = idx & 15;
        float4 v = *(const float4*)(atT + atChunk(k, p4));
        *((float4*)(g_attn + (size_t)(b * KK + k) * HWN + pix0) + p4) = v;
    }

    // --- A: per-k sums ---
    if (tid < KK) {
        int k = tid;
        float ssum = 0.f;
        for (int p4 = 0; p4 < 16; p4++) {
            float4 v = *(const float4*)(atT + atChunk(k, p4));
            ssum += v.x + v.y + v.z + v.w;
        }
        atomicAdd(&g_A[b * KK + k], ssum);
    }

    // --- fused S2 + cluster via mma: warp owns 32-c group + 8-j slice, all 4 k-tiles ---
    // cluster: attn split (exact) x tf32-x (2-term); S2: 3-term exact.
    // s-loop unrolled x2 for cross-iteration ILP (split chains overlap mma issue).
    {
        const int cbase = w * 32;
        const int j0 = w * 8;
        float dc[4][4][4];          // [ktile][ntile][frag]
        float ds[4][4];             // [ktile][frag]
#pragma unroll
        for (int kt = 0; kt < 4; kt++) {
#pragma unroll
            for (int nt = 0; nt < 4; nt++)
#pragma unroll
                for (int j = 0; j < 4; j++) dc[kt][nt][j] = 0.f;
#pragma unroll
            for (int j = 0; j < 4; j++) ds[kt][j] = 0.f;
        }

#pragma unroll 2
        for (int s = 0; s < 8; s++) {
            int p0 = s * 8;
            // cluster B fragments (x, pre-rounded tf32) — loaded ONCE per warp
            uint32_t bh[4][2];
#pragma unroll
            for (int nt = 0; nt < 4; nt++) {
                const float* bp = xsh + (cbase + 8 * nt + lq) * XS1 + p0;
                bh[nt][0] = fbits(bp[lr]);
                bh[nt][1] = fbits(bp[4 + lr]);
            }
            // S2 B fragments (attn, exact split)
            uint32_t sbh0, sbl0, sbh1, sbl1;
            tf32split(atT[atIdx(j0 + lq, p0 + lr)],     sbh0, sbl0);
            tf32split(atT[atIdx(j0 + lq, p0 + 4 + lr)], sbh1, sbl1);

#pragma unroll
            for (int kt = 0; kt < 4; kt++) {
                int k0 = kt * 16;
                uint32_t ah0, al0, ah1, al1, ah2, al2, ah3, al3;
                tf32split(atT[atIdx(k0 + lq,     p0 + lr)],     ah0, al0);
                tf32split(atT[atIdx(k0 + 8 + lq, p0 + lr)],     ah1, al1);
                tf32split(atT[atIdx(k0 + lq,     p0 + 4 + lr)], ah2, al2);
                tf32split(atT[atIdx(k0 + 8 + lq, p0 + 4 + lr)], ah3, al3);
#pragma unroll
                for (int nt = 0; nt < 4; nt++) {
                    mma8(dc[kt][nt], ah0, ah1, ah2, ah3, bh[nt][0], bh[nt][1]);
                    mma8(dc[kt][nt], al0, al1, al2, al3, bh[nt][0], bh[nt][1]);
                }
                mma8(ds[kt], ah0, ah1, ah2, ah3, sbh0, sbh1);
                mma8(ds[kt], ah0, ah1, ah2, ah3, sbl0, sbl1);
                mma8(ds[kt], al0, al1, al2, al3, sbh0, sbh1);
            }
        }

        // epilogues: float2 vector atomics
#pragma unroll
        for (int kt = 0; kt < 4; kt++) {
            int kr0 = kt * 16 + lq, kr1 = kr0 + 8;
#pragma unroll
            for (int nt = 0; nt < 4; nt++) {
                int c = cbase + 8 * nt + 2 * lr;
                atomicAdd((float2*)&g_cluster[(b * KK + kr0) * CC + c],
                          make_float2(dc[kt][nt][0], dc[kt][nt][1]));
                atomicAdd((float2*)&g_cluster[(b * KK + kr1) * CC + c],
                          make_float2(dc[kt][nt][2], dc[kt][nt][3]));
            }
            int jc = j0 + 2 * lr;
            atomicAdd((float2*)&g_S2[(b * KK + kr0) * KK + jc],
                      make_float2(ds[kt][0], ds[kt][1]));
            atomicAdd((float2*)&g_S2[(b * KK + kr1) * KK + jc],
                      make_float2(ds[kt][2], ds[kt][3]));
        }
    }
}

// ---------------- pass 2a: depthwise 7x7 on 8x8 grid + bias + silu ----------------
__global__ __launch_bounds__(256) void k2a(const float* __restrict__ dw_w,
                                           const float* __restrict__ dw_b) {
    extern __shared__ float s2[];
    float* cl  = s2;             // [64][256]
    float* dws = s2 + KK * CC;   // [256][49]
    int b = blockIdx.x, tid = threadIdx.x;
    int pos0 = blockIdx.y * 8;
    for (int i = tid; i < KK * CC / 4; i += 256)
        ((float4*)cl)[i] = ((const float4*)(g_cluster + b * KK * CC))[i];
    for (int i = tid; i < CC * 49; i += 256) dws[i] = dw_w[i];
    __syncthreads();
    int c = tid;
    float bias = dw_b[c];
    for (int pos = pos0; pos < pos0 + 8; pos++) {
        int i = pos >> 3, j = pos & 7;
        float sacc = bias;
        for (int di = 0; di < 7; di++) {
            int ii = i + di - 3;
            if (ii < 0 || ii >= 8) continue;
            for (int dj = 0; dj < 7; dj++) {
                int jj = j + dj - 3;
                if (jj < 0 || jj >= 8) continue;
                sacc = fmaf(cl[(ii * 8 + jj) * CC + c], dws[c * 49 + di * 7 + dj], sacc);
            }
        }
        float r = sacc / (1.f + expf(-sacc));   // silu
        g_ref[(b * KK + pos) * CC + c] = r;
    }
}

// ---------------- pass 2b: M = refined @ pw^T, analytic GN stats, Mhat/Bc ----------------
__global__ __launch_bounds__(512) void k2b(const float* __restrict__ pw_w,
                                           const float* __restrict__ pw_b,
                                           const float* __restrict__ gn_g,
                                           const float* __restrict__ gn_b) {
    extern __shared__ float s3[];
    float* rf     = s3;                // 16384
    float* S2s    = rf + 16384;        // 4096
    float* pwS    = S2s + 4096;        // 32*257 = 8224 (reused as T)
    float* Ms     = pwS + 8224;        // 64*33 = 2112
    float* As     = Ms + 2112;         // 64
    float* abar   = As + 64;           // 32
    float* ybar   = abar + 32;         // 32
    float* qs     = ybar + 32;         // 32
    float* alphaS = qs + 32;           // 32
    float* mug    = alphaS + 32;       // 4
    float* rstdg  = mug + 4;           // 4

    const int b = blockIdx.y;
    const int o0 = blockIdx.x * 32;
    const int tid = threadIdx.x;

    for (int i = tid; i < KK * CC / 4; i += 512)
        ((float4*)rf)[i] = ((const float4*)(g_ref + b * KK * CC))[i];
    for (int i = tid; i < KK * KK / 4; i += 512)
        ((float4*)S2s)[i] = ((const float4*)(g_S2 + b * KK * KK))[i];
    if (tid < KK) As[tid] = g_A[b * KK + tid];
    for (int i = tid; i < 32 * CC / 4; i += 512) {
        int o = i >> 6, c4 = i & 63;
        float4 v = ((const float4*)(pw_w + (o0 + o) * CC))[c4];
        float* dst = pwS + o * 257 + c4 * 4;
        dst[0] = v.x; dst[1] = v.y; dst[2] = v.z; dst[3] = v.w;
    }
    __syncthreads();

    // M[k][o] = sum_c rf[k][c] * pw[o][c]
    {
        int oG = tid & 31, k0 = (tid >> 5) * 4;
        float acc[4] = {};
        for (int c = 0; c < CC; c++) {
            float pv = pwS[oG * 257 + c];
#pragma unroll
            for (int i = 0; i < 4; i++)
                acc[i] = fmaf(rf[(k0 + i) * CC + c], pv, acc[i]);
        }
#pragma unroll
        for (int i = 0; i < 4; i++) Ms[(k0 + i) * 33 + oG] = acc[i];
    }
    __syncthreads();

    if (tid < 32) {
        float ssum = 0.f;
        for (int k = 0; k < KK; k++) ssum = fmaf(As[k], Ms[k * 33 + tid], ssum);
        float ab = ssum * (1.f / (float)HWN);
        abar[tid] = ab;
        ybar[tid] = pw_b[o0 + tid] + ab;
    }
    __syncthreads();

    for (int i = tid; i < KK * 32; i += 512) {
        int k = i >> 5, o = i & 31;
        Ms[k * 33 + o] -= abar[o];
    }
    __syncthreads();

    for (int i = tid; i < KK * 32; i += 512) {
        int k = i >> 5, o = i & 31;
        float t = 0.f;
        for (int k2 = 0; k2 < KK; k2++)
            t = fmaf(S2s[k * KK + k2], Ms[k2 * 33 + o], t);
        pwS[k * 33 + o] = t;
    }
    __syncthreads();

    if (tid < 32) {
        float q = 0.f;
        for (int k = 0; k < KK; k++)
            q = fmaf(Ms[k * 33 + tid], pwS[k * 33 + tid], q);
        qs[tid] = q;
    }
    __syncthreads();

    if (tid < 4) {
        float mu = 0.f;
#pragma unroll
        for (int j = 0; j < 8; j++) mu += ybar[tid * 8 + j];
        mu *= 0.125f;
        float v = 0.f, vq = 0.f;
#pragma unroll
        for (int j = 0; j < 8; j++) {
            float d = ybar[tid * 8 + j] - mu;
            v = fmaf(d, d, v);
            vq += qs[tid * 8 + j];
        }
        v = v * 0.125f + vq * (1.f / (8.f * (float)HWN));
        mug[tid] = mu;
        rstdg[tid] = rsqrtf(v + EPS);
    }
    __syncthreads();

    if (tid < 32) {
        int o = o0 + tid, g = tid >> 3;
        float a = gn_g[o] * rstdg[g];
        alphaS[tid] = a;
        g_Bc[b * CC + o] = gn_b[o] + a * (ybar[tid] - mug[g]);
    }
    __syncthreads();

    for (int i = tid; i < KK * 32; i += 512) {
        int k = i >> 5, oG = i & 31;
        g_Mhat[(b * KK + k) * CC + o0 + oG] = alphaS[oG] * Ms[k * 33 + oG];
    }
}

// ---------------- pass 3: out = x + attn @ Mhat + Bc ----------------
__global__ __launch_bounds__(512, 2) void k3(const float* __restrict__ x,
                                             float* __restrict__ out) {
    extern __shared__ float s4[];
    float* atS = s4;               // [64][132]
    float* MhS = s4 + KK * 132;    // [64][256]
    float* BcS = MhS + KK * CC;    // [256]

    const int b = blockIdx.y;
    const int pix0 = blockIdx.x * PTILE;
    const int tid = threadIdx.x;

#pragma unroll
    for (int it = 0; it < 4; it++) {
        int idx = it * 512 + tid;
        int k = idx >> 5, p4 = idx & 31;
        float4 v = *((const float4*)(g_attn + (size_t)(b * KK + k) * HWN + pix0) + p4);
        *((float4*)(atS + k * 132) + p4) = v;
    }
#pragma unroll
    for (int it = 0; it < 8; it++) {
        int idx = it * 512 + tid;
        ((float4*)MhS)[idx] = ((const float4*)(g_Mhat + (size_t)b * KK * CC))[idx];
    }
    if (tid < CC) BcS[tid] = g_Bc[b * CC + tid];
    __syncthreads();

    const int cg = tid >> 6;
    const int pp = tid & 63;
    const int p0 = 2 * pp;
    const int c0 = cg * 32;

    ull acc[2][16];
#pragma unroll
    for (int jc = 0; jc < 16; jc++) {
        ull bcv = *(const ull*)(BcS + c0 + 2 * jc);
        acc[0][jc] = bcv; acc[1][jc] = bcv;
    }

    for (int k = 0; k < KK; k++) {
        float2 af = *(const float2*)(atS + k * 132 + p0);
        ull ad0 = pk2(af.x, af.x), ad1 = pk2(af.y, af.y);
        const ulonglong2* mh = (const ulonglong2*)(MhS + k * CC + c0);
#pragma unroll
        for (int j4 = 0; j4 < 8; j4++) {
            ulonglong2 m = mh[j4];
            ffma2(acc[0][2 * j4],     ad0, m.x);
            ffma2(acc[0][2 * j4 + 1], ad0, m.y);
            ffma2(acc[1][2 * j4],     ad1, m.x);
            ffma2(acc[1][2 * j4 + 1], ad1, m.y);
        }
    }

#pragma unroll
    for (int jc = 0; jc < 16; jc++) {
        float2 v0 = unpk(acc[0][jc]);
        float2 v1 = unpk(acc[1][jc]);
        int ch0 = c0 + 2 * jc;
        size_t base0 = ((size_t)b * CC + ch0) * HWN + pix0 + p0;
        size_t base1 = base0 + HWN;
        float2 xv0 = __ldcs((const float2*)(x + base0));
        float2 xv1 = __ldcs((const float2*)(x + base1));
        float2 o0 = make_float2(xv0.x + v0.x, xv0.y + v1.x);
        float2 o1 = make_float2(xv1.x + v0.y, xv1.y + v1.y);
        __stcs((float2*)(out + base0), o0);
        __stcs((float2*)(out + base1), o1);
    }
}

// ---------------- launch ----------------
extern "C" void kernel_launch(void* const* d_in, const int* in_sizes, int n_in,
                              void* d_out, int out_size) {
    const float* x       = (const float*)d_in[0];
    const float* centers = (const float*)d_in[1];
    const float* dw_w    = (const float*)d_in[2];
    const float* dw_b    = (const float*)d_in[3];
    const float* pw_w    = (const float*)d_in[4];
    const float* pw_b    = (const float*)d_in[5];
    const float* gn_g    = (const float*)d_in[6];
    const float* gn_b    = (const float*)d_in[7];
    float* out = (float*)d_out;

    const int SM1  = (CC * XS1 + KK * 64) * 4;                           // 90112
    const int SM2A = (KK * CC + CC * 49) * 4;                            // 115712
    const int SM2B = (16384 + 4096 + 8224 + 2112 + 64 + 32 * 4 + 8) * 4; // 124064
    const int SM3  = (KK * 132 + KK * CC + CC) * 4;                      // 100352

    cudaFuncSetAttribute(k1,  cudaFuncAttributeMaxDynamicSharedMemorySize, SM1);
    cudaFuncSetAttribute(k2a, cudaFuncAttributeMaxDynamicSharedMemorySize, SM2A);
    cudaFuncSetAttribute(k2b, cudaFuncAttributeMaxDynamicSharedMemorySize, SM2B);
    cudaFuncSetAttribute(k3,  cudaFuncAttributeMaxDynamicSharedMemorySize, SM3);

    k_init_a<<<128, 256>>>();
    k_init_b<<<64, 256>>>();
    k_init_c<<<64, 256>>>(centers);
    k1<<<dim3(HWN / PT1, BB), 256, SM1>>>(x);
    k2a<<<dim3(BB, 8), 256, SM2A>>>(dw_w, dw_b);
    k2b<<<dim3(8, BB), 512, SM2B>>>(pw_w, pw_b, gn_g, gn_b);
    k3<<<dim3(HWN / PTILE, BB), 512, SM3>>>(x, out);
}

// round 17
// speedup vs baseline: 2.5768x; 2.5768x over previous
#include <cuda_runtime.h>
#include <cuda_bf16.h>
#include <cstdint>

#define BB 8
#define CC 256
#define HWN 16384
#define KK 64
#define EPS 1e-5f
#define PT1 64       // k1 pixel tile
#define XS1 72       // k1 xs[c][p] row stride
#define PT3 64       // k3 pixel tile
#define AS3 72       // k3 atS row stride (16B-aligned rows)

typedef unsigned long long ull;

// ---------------- helpers ----------------
__device__ __forceinline__ ull pk2(float lo, float hi) {
    ull d; asm("mov.b64 %0, {%1, %2};" : "=l"(d) : "f"(lo), "f"(hi)); return d;
}
__device__ __forceinline__ float2 unpk(ull v) {
    float2 r; asm("mov.b64 {%0, %1}, %2;" : "=f"(r.x), "=f"(r.y) : "l"(v)); return r;
}
__device__ __forceinline__ void ffma2(ull& d, ull a, ull b) {
    asm("fma.rn.f32x2 %0, %1, %2, %0;" : "+l"(d) : "l"(a), "l"(b));
}
__device__ __forceinline__ uint32_t to_tf32(float f) {
    uint32_t u; asm("cvt.rna.tf32.f32 %0, %1;" : "=r"(u) : "f"(f)); return u;
}
__device__ __forceinline__ void tf32split(float v, uint32_t& hi, uint32_t& lo) {
    uint32_t h = to_tf32(v);
    hi = h;
    lo = to_tf32(v - __uint_as_float(h));
}
__device__ __forceinline__ void mma8(float* d, uint32_t a0, uint32_t a1,
                                     uint32_t a2, uint32_t a3,
                                     uint32_t b0, uint32_t b1) {
    asm("mma.sync.aligned.m16n8k8.row.col.f32.tf32.tf32.f32 "
        "{%0,%1,%2,%3}, {%4,%5,%6,%7}, {%8,%9}, {%0,%1,%2,%3};"
        : "+f"(d[0]), "+f"(d[1]), "+f"(d[2]), "+f"(d[3])
        : "r"(a0), "r"(a1), "r"(a2), "r"(a3), "r"(b0), "r"(b1));
}
__device__ __forceinline__ uint32_t fbits(float f) { return __float_as_uint(f); }

// atT swizzled layout, row stride 64 floats = 16 chunks of 16B.
__device__ __forceinline__ int atIdx(int k, int p) {
    return k * 64 + ((((p >> 2) ^ (k & 7)) << 2) | (p & 3));
}
__device__ __forceinline__ int atChunk(int k, int p4) {
    return k * 64 + ((p4 ^ (k & 7)) << 2);
}

// ---------------- device scratch (no allocation) ----------------
__device__ float g_attn[(size_t)BB * KK * HWN];   // [b][k][n]  32MB
__device__ float g_cluster[BB * KK * CC];
__device__ float g_A[BB * KK];
__device__ float g_S2[BB * KK * KK];
__device__ float g_AF[32 * 4 * 32 * 4];           // tf32 A-fragments for sim
__device__ float g_ref[BB * KK * CC];
__device__ float g_Mhat[BB * KK * CC];
__device__ float g_Bc[BB * CC];

// ---------------- init ----------------
__global__ void k_init_a() {
    int i = blockIdx.x * blockDim.x + threadIdx.x;
    int st = gridDim.x * blockDim.x;
    for (int t = i; t < BB * KK * CC; t += st) g_cluster[t] = 0.f;
}
__global__ void k_init_b() {
    int i = blockIdx.x * blockDim.x + threadIdx.x;
    int st = gridDim.x * blockDim.x;
    for (int t = i; t < BB * KK * KK; t += st) g_S2[t] = 0.f;
    for (int t = i; t < BB * KK; t += st) g_A[t] = 0.f;
}
__global__ void k_init_c(const float* __restrict__ centers) {
    int i = blockIdx.x * blockDim.x + threadIdx.x;
    int st = gridDim.x * blockDim.x;
    for (int t = i; t < 32 * 4 * 32 * 4; t += st) {
        int j  = t & 3;
        int l  = (t >> 2) & 31;
        int kt = (t >> 7) & 3;
        int s  = t >> 9;
        int k = kt * 16 + (l >> 2) + 8 * (j & 1);
        int c = s * 8 + (l & 3) + 4 * (j >> 1);
        uint32_t u = to_tf32(centers[k * CC + c]);
        g_AF[t] = __uint_as_float(u);
    }
}

// ---------------- pass 1 (R13 structure): mma-sim -> softmax -> attn, A, fused S2+cluster ----------------
__global__ __launch_bounds__(256, 2) void k1(const float* __restrict__ x) {
    extern __shared__ float s1[];
    float* xsh = s1;                 // [256][72] : tf32-rounded x, xs[c][p]
    float* atT = s1 + CC * XS1;      // swizzled [64]x[64]

    const int b = blockIdx.y;
    const int pix0 = blockIdx.x * PT1;
    const int tid = threadIdx.x;
    const float* xb = x + (size_t)b * CC * HWN;

    const int w = tid >> 5, l = tid & 31;
    const int lq = l >> 2, lr = l & 3;

#pragma unroll
    for (int it = 0; it < 16; it++) {
        int idx = it * 256 + tid;
        int c = idx >> 4, p4 = idx & 15;
        float4 v = __ldcs((const float4*)(xb + (size_t)c * HWN + pix0) + p4);
        v.x = __uint_as_float(to_tf32(v.x));
        v.y = __uint_as_float(to_tf32(v.y));
        v.z = __uint_as_float(to_tf32(v.z));
        v.w = __uint_as_float(to_tf32(v.w));
        *((float4*)(xsh + c * XS1) + p4) = v;
    }
    __syncthreads();

    // --- sim via tensor cores ---
    {
        const int kt = w & 3;
        const int k0 = kt * 16;
        const int pbase = (w >> 2) * 32;
        float d[4][4];
#pragma unroll
        for (int t = 0; t < 4; t++)
#pragma unroll
            for (int j = 0; j < 4; j++) d[t][j] = 0.f;

        for (int s = 0; s < 32; s++) {
            float4 af = __ldg(((const float4*)g_AF) + (s * 4 + kt) * 32 + l);
            uint32_t a0 = fbits(af.x), a1 = fbits(af.y);
            uint32_t a2 = fbits(af.z), a3 = fbits(af.w);
            const float* xrow0 = xsh + (8 * s + lr) * XS1 + lq;
            const float* xrow1 = xrow0 + 4 * XS1;
#pragma unroll
            for (int t = 0; t < 4; t++) {
                int p0 = pbase + t * 8;
                mma8(d[t], a0, a1, a2, a3, fbits(xrow0[p0]), fbits(xrow1[p0]));
            }
        }
        const float sc = 0.0625f;
#pragma unroll
        for (int t = 0; t < 4; t++) {
            int p0 = pbase + t * 8;
            int kr = k0 + lq, pc = p0 + 2 * lr;
            atT[atIdx(kr,     pc)]     = d[t][0] * sc;
            atT[atIdx(kr,     pc + 1)] = d[t][1] * sc;
            atT[atIdx(kr + 8, pc)]     = d[t][2] * sc;
            atT[atIdx(kr + 8, pc + 1)] = d[t][3] * sc;
        }
    }
    __syncthreads();

    // --- softmax over k per pixel ---
    if (tid < PT1) {
        int p = tid;
        float v[KK];
        float m = -1e30f;
#pragma unroll
        for (int k = 0; k < KK; k++) { v[k] = atT[atIdx(k, p)]; m = fmaxf(m, v[k]); }
        float ssum = 0.f;
#pragma unroll
        for (int k = 0; k < KK; k++) { v[k] = __expf(v[k] - m); ssum += v[k]; }
        float inv = 1.f / ssum;
#pragma unroll
        for (int k = 0; k < KK; k++) atT[atIdx(k, p)] = v[k] * inv;
    }
    __syncthreads();

    // --- attn writeout ---
#pragma unroll
    for (int it = 0; it < 4; it++) {
        int idx = it * 256 + tid;
        int k = idx >> 4, p4 = idx & 15;
        float4 v = *(const float4*)(atT + atChunk(k, p4));
        *((float4*)(g_attn + (size_t)(b * KK + k) * HWN + pix0) + p4) = v;
    }

    // --- A: per-k sums ---
    if (tid < KK) {
        int k = tid;
        float ssum = 0.f;
        for (int p4 = 0; p4 < 16; p4++) {
            float4 v = *(const float4*)(atT + atChunk(k, p4));
            ssum += v.x + v.y + v.z + v.w;
        }
        atomicAdd(&g_A[b * KK + k], ssum);
    }

    // --- fused S2 + cluster via mma ---
    {
        const int cbase = w * 32;
        const int j0 = w * 8;
        float dc[4][4][4];
        float ds[4][4];
#pragma unroll
        for (int kt = 0; kt < 4; kt++) {
#pragma unroll
            for (int nt = 0; nt < 4; nt++)
#pragma unroll
                for (int j = 0; j < 4; j++) dc[kt][nt][j] = 0.f;
#pragma unroll
            for (int j = 0; j < 4; j++) ds[kt][j] = 0.f;
        }

        for (int s = 0; s < 8; s++) {
            int p0 = s * 8;
            uint32_t bh[4][2];
#pragma unroll
            for (int nt = 0; nt < 4; nt++) {
                const float* bp = xsh + (cbase + 8 * nt + lq) * XS1 + p0;
                bh[nt][0] = fbits(bp[lr]);
                bh[nt][1] = fbits(bp[4 + lr]);
            }
            uint32_t sbh0, sbl0, sbh1, sbl1;
            tf32split(atT[atIdx(j0 + lq, p0 + lr)],     sbh0, sbl0);
            tf32split(atT[atIdx(j0 + lq, p0 + 4 + lr)], sbh1, sbl1);

#pragma unroll
            for (int kt = 0; kt < 4; kt++) {
                int k0 = kt * 16;
                uint32_t ah0, al0, ah1, al1, ah2, al2, ah3, al3;
                tf32split(atT[atIdx(k0 + lq,     p0 + lr)],     ah0, al0);
                tf32split(atT[atIdx(k0 + 8 + lq, p0 + lr)],     ah1, al1);
                tf32split(atT[atIdx(k0 + lq,     p0 + 4 + lr)], ah2, al2);
                tf32split(atT[atIdx(k0 + 8 + lq, p0 + 4 + lr)], ah3, al3);
#pragma unroll
                for (int nt = 0; nt < 4; nt++) {
                    mma8(dc[kt][nt], ah0, ah1, ah2, ah3, bh[nt][0], bh[nt][1]);
                    mma8(dc[kt][nt], al0, al1, al2, al3, bh[nt][0], bh[nt][1]);
                }
                mma8(ds[kt], ah0, ah1, ah2, ah3, sbh0, sbh1);
                mma8(ds[kt], ah0, ah1, ah2, ah3, sbl0, sbl1);
                mma8(ds[kt], al0, al1, al2, al3, sbh0, sbh1);
            }
        }

#pragma unroll
        for (int kt = 0; kt < 4; kt++) {
            int kr0 = kt * 16 + lq, kr1 = kr0 + 8;
#pragma unroll
            for (int nt = 0; nt < 4; nt++) {
                int c = cbase + 8 * nt + 2 * lr;
                atomicAdd((float2*)&g_cluster[(b * KK + kr0) * CC + c],
                          make_float2(dc[kt][nt][0], dc[kt][nt][1]));
                atomicAdd((float2*)&g_cluster[(b * KK + kr1) * CC + c],
                          make_float2(dc[kt][nt][2], dc[kt][nt][3]));
            }
            int jc = j0 + 2 * lr;
            atomicAdd((float2*)&g_S2[(b * KK + kr0) * KK + jc],
                      make_float2(ds[kt][0], ds[kt][1]));
            atomicAdd((float2*)&g_S2[(b * KK + kr1) * KK + jc],
                      make_float2(ds[kt][2], ds[kt][3]));
        }
    }
}

// ---------------- pass 2a ----------------
__global__ __launch_bounds__(256) void k2a(const float* __restrict__ dw_w,
                                           const float* __restrict__ dw_b) {
    extern __shared__ float s2[];
    float* cl  = s2;
    float* dws = s2 + KK * CC;
    int b = blockIdx.x, tid = threadIdx.x;
    int pos0 = blockIdx.y * 8;
    for (int i = tid; i < KK * CC / 4; i += 256)
        ((float4*)cl)[i] = ((const float4*)(g_cluster + b * KK * CC))[i];
    for (int i = tid; i < CC * 49; i += 256) dws[i] = dw_w[i];
    __syncthreads();
    int c = tid;
    float bias = dw_b[c];
    for (int pos = pos0; pos < pos0 + 8; pos++) {
        int i = pos >> 3, j = pos & 7;
        float sacc = bias;
        for (int di = 0; di < 7; di++) {
            int ii = i + di - 3;
            if (ii < 0 || ii >= 8) continue;
            for (int dj = 0; dj < 7; dj++) {
                int jj = j + dj - 3;
                if (jj < 0 || jj >= 8) continue;
                sacc = fmaf(cl[(ii * 8 + jj) * CC + c], dws[c * 49 + di * 7 + dj], sacc);
            }
        }
        float r = sacc / (1.f + expf(-sacc));
        g_ref[(b * KK + pos) * CC + c] = r;
    }
}

// ---------------- pass 2b ----------------
__global__ __launch_bounds__(512) void k2b(const float* __restrict__ pw_w,
                                           const float* __restrict__ pw_b,
                                           const float* __restrict__ gn_g,
                                           const float* __restrict__ gn_b) {
    extern __shared__ float s3[];
    float* rf     = s3;
    float* S2s    = rf + 16384;
    float* pwS    = S2s + 4096;
    float* Ms     = pwS + 8224;
    float* As     = Ms + 2112;
    float* abar   = As + 64;
    float* ybar   = abar + 32;
    float* qs     = ybar + 32;
    float* alphaS = qs + 32;
    float* mug    = alphaS + 32;
    float* rstdg  = mug + 4;

    const int b = blockIdx.y;
    const int o0 = blockIdx.x * 32;
    const int tid = threadIdx.x;

    for (int i = tid; i < KK * CC / 4; i += 512)
        ((float4*)rf)[i] = ((const float4*)(g_ref + b * KK * CC))[i];
    for (int i = tid; i < KK * KK / 4; i += 512)
        ((float4*)S2s)[i] = ((const float4*)(g_S2 + b * KK * KK))[i];
    if (tid < KK) As[tid] = g_A[b * KK + tid];
    for (int i = tid; i < 32 * CC / 4; i += 512) {
        int o = i >> 6, c4 = i & 63;
        float4 v = ((const float4*)(pw_w + (o0 + o) * CC))[c4];
        float* dst = pwS + o * 257 + c4 * 4;
        dst[0] = v.x; dst[1] = v.y; dst[2] = v.z; dst[3] = v.w;
    }
    __syncthreads();

    {
        int oG = tid & 31, k0 = (tid >> 5) * 4;
        float acc[4] = {};
        for (int c = 0; c < CC; c++) {
            float pv = pwS[oG * 257 + c];
#pragma unroll
            for (int i = 0; i < 4; i++)
                acc[i] = fmaf(rf[(k0 + i) * CC + c], pv, acc[i]);
        }
#pragma unroll
        for (int i = 0; i < 4; i++) Ms[(k0 + i) * 33 + oG] = acc[i];
    }
    __syncthreads();

    if (tid < 32) {
        float ssum = 0.f;
        for (int k = 0; k < KK; k++) ssum = fmaf(As[k], Ms[k * 33 + tid], ssum);
        float ab = ssum * (1.f / (float)HWN);
        abar[tid] = ab;
        ybar[tid] = pw_b[o0 + tid] + ab;
    }
    __syncthreads();

    for (int i = tid; i < KK * 32; i += 512) {
        int k = i >> 5, o = i & 31;
        Ms[k * 33 + o] -= abar[o];
    }
    __syncthreads();

    for (int i = tid; i < KK * 32; i += 512) {
        int k = i >> 5, o = i & 31;
        float t = 0.f;
        for (int k2 = 0; k2 < KK; k2++)
            t = fmaf(S2s[k * KK + k2], Ms[k2 * 33 + o], t);
        pwS[k * 33 + o] = t;
    }
    __syncthreads();

    if (tid < 32) {
        float q = 0.f;
        for (int k = 0; k < KK; k++)
            q = fmaf(Ms[k * 33 + tid], pwS[k * 33 + tid], q);
        qs[tid] = q;
    }
    __syncthreads();

    if (tid < 4) {
        float mu = 0.f;
#pragma unroll
        for (int j = 0; j < 8; j++) mu += ybar[tid * 8 + j];
        mu *= 0.125f;
        float v = 0.f, vq = 0.f;
#pragma unroll
        for (int j = 0; j < 8; j++) {
            float d = ybar[tid * 8 + j] - mu;
            v = fmaf(d, d, v);
            vq += qs[tid * 8 + j];
        }
        v = v * 0.125f + vq * (1.f / (8.f * (float)HWN));
        mug[tid] = mu;
        rstdg[tid] = rsqrtf(v + EPS);
    }
    __syncthreads();

    if (tid < 32) {
        int o = o0 + tid, g = tid >> 3;
        float a = gn_g[o] * rstdg[g];
        alphaS[tid] = a;
        g_Bc[b * CC + o] = gn_b[o] + a * (ybar[tid] - mug[g]);
    }
    __syncthreads();

    for (int i = tid; i < KK * 32; i += 512) {
        int k = i >> 5, oG = i & 31;
        g_Mhat[(b * KK + k) * CC + o0 + oG] = alphaS[oG] * Ms[k * 33 + oG];
    }
}

// ---------------- pass 3: out = x + attn @ Mhat + Bc ----------------
// 256 threads, 64-pixel tile, 2 CTAs/SM (no register spill: natural 128-reg cap).
__global__ __launch_bounds__(256, 2) void k3(const float* __restrict__ x,
                                             float* __restrict__ out) {
    extern __shared__ float s4[];
    float* atS = s4;               // [64][72]
    float* MhS = s4 + KK * AS3;    // [64][256]
    float* BcS = MhS + KK * CC;    // [256]

    const int b = blockIdx.y;
    const int pix0 = blockIdx.x * PT3;
    const int tid = threadIdx.x;

    // attn tile: 64k x 64p = 1024 float4, 4 per thread
#pragma unroll
    for (int it = 0; it < 4; it++) {
        int idx = it * 256 + tid;
        int k = idx >> 4, p4 = idx & 15;
        float4 v = *((const float4*)(g_attn + (size_t)(b * KK + k) * HWN + pix0) + p4);
        *((float4*)(atS + k * AS3) + p4) = v;
    }
    // Mhat: 4096 float4, 16 per thread
#pragma unroll
    for (int it = 0; it < 16; it++) {
        int idx = it * 256 + tid;
        ((float4*)MhS)[idx] = ((const float4*)(g_Mhat + (size_t)b * KK * CC))[idx];
    }
    if (tid < CC) BcS[tid] = g_Bc[b * CC + tid];
    __syncthreads();

    // thread = (pixel pair pp in 0..31, channel group cg in 0..7); cg warp-uniform
    const int cg = tid >> 5;
    const int pp = tid & 31;
    const int p0 = 2 * pp;
    const int c0 = cg * 32;

    ull acc[2][16];
#pragma unroll
    for (int jc = 0; jc < 16; jc++) {
        ull bcv = *(const ull*)(BcS + c0 + 2 * jc);
        acc[0][jc] = bcv; acc[1][jc] = bcv;
    }

    for (int k = 0; k < KK; k++) {
        float2 af = *(const float2*)(atS + k * AS3 + p0);
        ull ad0 = pk2(af.x, af.x), ad1 = pk2(af.y, af.y);
        const ulonglong2* mh = (const ulonglong2*)(MhS + k * CC + c0);
#pragma unroll
        for (int j4 = 0; j4 < 8; j4++) {
            ulonglong2 m = mh[j4];
            ffma2(acc[0][2 * j4],     ad0, m.x);
            ffma2(acc[0][2 * j4 + 1], ad0, m.y);
            ffma2(acc[1][2 * j4],     ad1, m.x);
            ffma2(acc[1][2 * j4 + 1], ad1, m.y);
        }
    }

#pragma unroll
    for (int jc = 0; jc < 16; jc++) {
        float2 v0 = unpk(acc[0][jc]);
        float2 v1 = unpk(acc[1][jc]);
        int ch0 = c0 + 2 * jc;
        size_t base0 = ((size_t)b * CC + ch0) * HWN + pix0 + p0;
        size_t base1 = base0 + HWN;
        float2 xv0 = __ldcs((const float2*)(x + base0));
        float2 xv1 = __ldcs((const float2*)(x + base1));
        float2 o0 = make_float2(xv0.x + v0.x, xv0.y + v1.x);
        float2 o1 = make_float2(xv1.x + v0.y, xv1.y + v1.y);
        __stcs((float2*)(out + base0), o0);
        __stcs((float2*)(out + base1), o1);
    }
}

// ---------------- launch ----------------
extern "C" void kernel_launch(void* const* d_in, const int* in_sizes, int n_in,
                              void* d_out, int out_size) {
    const float* x       = (const float*)d_in[0];
    const float* centers = (const float*)d_in[1];
    const float* dw_w    = (const float*)d_in[2];
    const float* dw_b    = (const float*)d_in[3];
    const float* pw_w    = (const float*)d_in[4];
    const float* pw_b    = (const float*)d_in[5];
    const float* gn_g    = (const float*)d_in[6];
    const float* gn_b    = (const float*)d_in[7];
    float* out = (float*)d_out;

    const int SM1  = (CC * XS1 + KK * 64) * 4;                           // 90112
    const int SM2A = (KK * CC + CC * 49) * 4;                            // 115712
    const int SM2B = (16384 + 4096 + 8224 + 2112 + 64 + 32 * 4 + 8) * 4; // 124064
    const int SM3  = (KK * AS3 + KK * CC + CC) * 4;                      // 85504

    cudaFuncSetAttribute(k1,  cudaFuncAttributeMaxDynamicSharedMemorySize, SM1);
    cudaFuncSetAttribute(k2a, cudaFuncAttributeMaxDynamicSharedMemorySize, SM2A);
    cudaFuncSetAttribute(k2b, cudaFuncAttributeMaxDynamicSharedMemorySize, SM2B);
    cudaFuncSetAttribute(k3,  cudaFuncAttributeMaxDynamicSharedMemorySize, SM3);

    k_init_a<<<128, 256>>>();
    k_init_b<<<64, 256>>>();
    k_init_c<<<64, 256>>>(centers);
    k1<<<dim3(HWN / PT1, BB), 256, SM1>>>(x);
    k2a<<<dim3(BB, 8), 256, SM2A>>>(dw_w, dw_b);
    k2b<<<dim3(8, BB), 512, SM2B>>>(pw_w, pw_b, gn_g, gn_b);
    k3<<<dim3(HWN / PT3, BB), 256, SM3>>>(x, out);
}